// round 1
// baseline (speedup 1.0000x reference)
#include <cuda_runtime.h>
#include <cuda_bf16.h>

// Problem: B=8, S=2048, K=256, fp32.
// d[b,i,j] = max( ||x_i||^2 + ||x_j||^2 - 2 * <x_i, x_j>, 0 )

#define BATCH 8
#define SEQ   2048
#define RANK  256

// Scratch for per-row squared norms (no cudaMalloc allowed).
__device__ float g_sq_norms[BATCH * SEQ];

// ---------------------------------------------------------------------------
// Kernel 1: per-row squared norms. 16384 rows, one thread per row.
// ---------------------------------------------------------------------------
__global__ void norms_kernel(const float* __restrict__ x) {
    int row = blockIdx.x * blockDim.x + threadIdx.x;
    if (row >= BATCH * SEQ) return;
    const float4* p = reinterpret_cast<const float4*>(x + (size_t)row * RANK);
    float s = 0.0f;
#pragma unroll 16
    for (int q = 0; q < RANK / 4; q++) {
        float4 v = p[q];
        s = fmaf(v.x, v.x, s);
        s = fmaf(v.y, v.y, s);
        s = fmaf(v.z, v.z, s);
        s = fmaf(v.w, v.w, s);
    }
    g_sq_norms[row] = s;
}

// ---------------------------------------------------------------------------
// Kernel 2: batched SYRK-like distance kernel.
// 128x128 output tile per block, 256 threads, 8x8 micro-tile per thread,
// BK=8 shared-memory K-slices.
// ---------------------------------------------------------------------------
#define BM 128
#define BN 128
#define BK 8

__global__ __launch_bounds__(256, 2)
void dist_kernel(const float* __restrict__ x, float* __restrict__ out) {
    __shared__ float As[BK][BM];   // [k][i] layout for conflict-free reads
    __shared__ float Bs[BK][BN];   // [k][j]

    const int b  = blockIdx.z;
    const int i0 = blockIdx.y * BM;
    const int j0 = blockIdx.x * BN;

    const float* __restrict__ Xb = x + (size_t)b * SEQ * RANK;

    const int t  = threadIdx.x;        // 0..255
    const int tx = t & 15;             // 16 threads along j
    const int ty = t >> 4;             // 16 threads along i

    // Loader mapping: each thread loads one float4 of A and one of B per K-step.
    const int lrow = t >> 1;           // 0..127
    const int lk4  = (t & 1) * 4;      // 0 or 4

    float acc[8][8];
#pragma unroll
    for (int m = 0; m < 8; m++)
#pragma unroll
        for (int n = 0; n < 8; n++)
            acc[m][n] = 0.0f;

    const float* aptr = Xb + (size_t)(i0 + lrow) * RANK + lk4;
    const float* bptr = Xb + (size_t)(j0 + lrow) * RANK + lk4;

    for (int k0 = 0; k0 < RANK; k0 += BK) {
        float4 av = *reinterpret_cast<const float4*>(aptr + k0);
        float4 bv = *reinterpret_cast<const float4*>(bptr + k0);

        __syncthreads();   // guard against overwriting tiles still being read
        As[lk4 + 0][lrow] = av.x;
        As[lk4 + 1][lrow] = av.y;
        As[lk4 + 2][lrow] = av.z;
        As[lk4 + 3][lrow] = av.w;
        Bs[lk4 + 0][lrow] = bv.x;
        Bs[lk4 + 1][lrow] = bv.y;
        Bs[lk4 + 2][lrow] = bv.z;
        Bs[lk4 + 3][lrow] = bv.w;
        __syncthreads();

#pragma unroll
        for (int kk = 0; kk < BK; kk++) {
            float ra[8], rb[8];
            *reinterpret_cast<float4*>(&ra[0]) =
                *reinterpret_cast<const float4*>(&As[kk][ty * 8]);
            *reinterpret_cast<float4*>(&ra[4]) =
                *reinterpret_cast<const float4*>(&As[kk][ty * 8 + 4]);
            *reinterpret_cast<float4*>(&rb[0]) =
                *reinterpret_cast<const float4*>(&Bs[kk][tx * 8]);
            *reinterpret_cast<float4*>(&rb[4]) =
                *reinterpret_cast<const float4*>(&Bs[kk][tx * 8 + 4]);
#pragma unroll
            for (int m = 0; m < 8; m++)
#pragma unroll
                for (int n = 0; n < 8; n++)
                    acc[m][n] = fmaf(ra[m], rb[n], acc[m][n]);
        }
    }

    // Epilogue: d = ni + nj - 2*dot, clamp to 0, vectorized stores.
    float ni[8], nj[8];
#pragma unroll
    for (int m = 0; m < 8; m++)
        ni[m] = g_sq_norms[b * SEQ + i0 + ty * 8 + m];
#pragma unroll
    for (int n = 0; n < 8; n++)
        nj[n] = g_sq_norms[b * SEQ + j0 + tx * 8 + n];

#pragma unroll
    for (int m = 0; m < 8; m++) {
        float* orow = out + ((size_t)b * SEQ + (i0 + ty * 8 + m)) * SEQ + j0 + tx * 8;
        float v[8];
#pragma unroll
        for (int n = 0; n < 8; n++) {
            float d = fmaf(-2.0f, acc[m][n], ni[m] + nj[n]);
            v[n] = fmaxf(d, 0.0f);
        }
        *reinterpret_cast<float4*>(orow)     = *reinterpret_cast<float4*>(&v[0]);
        *reinterpret_cast<float4*>(orow + 4) = *reinterpret_cast<float4*>(&v[4]);
    }
}

// ---------------------------------------------------------------------------
extern "C" void kernel_launch(void* const* d_in, const int* in_sizes, int n_in,
                              void* d_out, int out_size) {
    (void)in_sizes; (void)n_in; (void)out_size;
    const float* x = (const float*)d_in[0];
    float* out = (float*)d_out;

    norms_kernel<<<(BATCH * SEQ + 255) / 256, 256>>>(x);

    dim3 grid(SEQ / BN, SEQ / BM, BATCH);   // (16, 16, 8)
    dist_kernel<<<grid, 256>>>(x, out);
}

// round 3
// speedup vs baseline: 2.2948x; 2.2948x over previous
#include <cuda_runtime.h>
#include <cuda_bf16.h>
#include <cstdint>

// d[b,i,j] = max(||x_i||^2 + ||x_j||^2 - 2 <x_i,x_j>, 0),  B=8, S=2048, K=256 fp32.
// Strategy: hi/lo bf16 split concatenated along K (K'=512); warp-level
// mma.sync bf16 GEMM (compute_100-safe); exact fp32 norms in epilogue.

#define BATCH 8
#define SEQ   2048
#define RANK  256
#define RANK2 512          // hi || lo

// ---------------- scratch (no cudaMalloc allowed) ----------------
__device__ __nv_bfloat16 g_y[(size_t)BATCH * SEQ * RANK2];   // 16 MB
__device__ float g_sq_norms[BATCH * SEQ];

// ---------------- PTX helpers (all sm_80-era, compute_100-safe) ----------
__device__ __forceinline__ uint32_t smem_to_u32(const void* p) {
    uint32_t a;
    asm("{ .reg .u64 t; cvta.to.shared.u64 t, %1; cvt.u32.u64 %0, t; }" : "=r"(a) : "l"(p));
    return a;
}
#define CP_ASYNC_CG(dst, src) \
    asm volatile("cp.async.cg.shared.global [%0], [%1], 16;" :: "r"(dst), "l"(src))
#define CP_ASYNC_COMMIT() asm volatile("cp.async.commit_group;" ::: "memory")
#define CP_ASYNC_WAIT1()  asm volatile("cp.async.wait_group 1;" ::: "memory")
#define CP_ASYNC_WAIT0()  asm volatile("cp.async.wait_group 0;" ::: "memory")

#define LDSM_X4(r0, r1, r2, r3, addr) \
    asm volatile("ldmatrix.sync.aligned.m8n8.x4.shared.b16 {%0,%1,%2,%3}, [%4];" \
                 : "=r"(r0), "=r"(r1), "=r"(r2), "=r"(r3) : "r"(addr))

#define MMA16816(c, a, b0, b1) \
    asm volatile("mma.sync.aligned.m16n8k16.row.col.f32.bf16.bf16.f32 " \
                 "{%0,%1,%2,%3}, {%4,%5,%6,%7}, {%8,%9}, {%0,%1,%2,%3};" \
                 : "+f"((c)[0]), "+f"((c)[1]), "+f"((c)[2]), "+f"((c)[3]) \
                 : "r"((a)[0]), "r"((a)[1]), "r"((a)[2]), "r"((a)[3]), \
                   "r"(b0), "r"(b1))

#define SWZ(off) ((off) ^ (((off) >> 3) & 0x70))

// ---------------------------------------------------------------------------
// prep: fused hi/lo bf16 split + exact fp32 row norms. One warp per row.
// ---------------------------------------------------------------------------
__global__ __launch_bounds__(128) void prep_kernel(const float* __restrict__ x) {
    int row = blockIdx.x * 4 + (threadIdx.x >> 5);
    int lid = threadIdx.x & 31;
    const float* xr = x + (size_t)row * RANK + lid * 8;
    __nv_bfloat16* yr = g_y + (size_t)row * RANK2 + lid * 8;

    float4 v0 = *reinterpret_cast<const float4*>(xr);
    float4 v1 = *reinterpret_cast<const float4*>(xr + 4);

    float e[8] = {v0.x, v0.y, v0.z, v0.w, v1.x, v1.y, v1.z, v1.w};
    alignas(16) __nv_bfloat162 h[4];
    alignas(16) __nv_bfloat162 l[4];
    float s = 0.0f;
#pragma unroll
    for (int q = 0; q < 4; q++) {
        float a = e[2 * q], bvv = e[2 * q + 1];
        s = fmaf(a, a, s);
        s = fmaf(bvv, bvv, s);
        __nv_bfloat16 ha = __float2bfloat16_rn(a);
        __nv_bfloat16 hb = __float2bfloat16_rn(bvv);
        __nv_bfloat16 la = __float2bfloat16_rn(a - __bfloat162float(ha));
        __nv_bfloat16 lb = __float2bfloat16_rn(bvv - __bfloat162float(hb));
        h[q] = __nv_bfloat162(ha, hb);
        l[q] = __nv_bfloat162(la, lb);
    }
    *reinterpret_cast<uint4*>(yr)        = *reinterpret_cast<uint4*>(h);
    *reinterpret_cast<uint4*>(yr + RANK) = *reinterpret_cast<uint4*>(l);

#pragma unroll
    for (int m = 16; m > 0; m >>= 1) s += __shfl_xor_sync(0xffffffffu, s, m);
    if (lid == 0) g_sq_norms[row] = s;
}

// ---------------------------------------------------------------------------
// Main GEMM: 128x128 CTA tile, 8 warps (2x4), warp tile 64x32, BK=64,
// cp.async double buffer, ldmatrix + mma.sync m16n8k16 bf16.
// ---------------------------------------------------------------------------
#define BK          64
#define NCHUNK      (RANK2 / BK)        // 8
#define OPER_BYTES  16384               // 128 rows x 128 B (64 bf16)
#define STAGE_BYTES 32768               // A + B, one stage
#define SMEM_TOTAL  (2 * STAGE_BYTES)   // 64 KB

__global__ __launch_bounds__(256, 1)
void dist_mma_kernel(float* __restrict__ out) {
    extern __shared__ __align__(128) char smem[];
    const uint32_t smem_base = smem_to_u32(smem);

    const int t = threadIdx.x;
    const int l = t & 31;
    const int w = t >> 5;
    const int wm = w >> 2;          // 0..1
    const int wn = w & 3;           // 0..3
    const int m0 = wm * 64;         // warp tile origin within CTA tile
    const int n0 = wn * 32;

    const int b  = blockIdx.z;
    const int i0 = blockIdx.y * 128;
    const int j0 = blockIdx.x * 128;

    const __nv_bfloat16* __restrict__ Ag = g_y + (size_t)(b * SEQ + i0) * RANK2;
    const __nv_bfloat16* __restrict__ Bg = g_y + (size_t)(b * SEQ + j0) * RANK2;

    // ---- loaders: 256 threads, each loads 4x16B for A and 4x16B for B ----
    const int lrow = t >> 1;            // 0..127
    const int lh   = t & 1;             // which 64B half of the 128B row

    auto load_chunk = [&](int c, int s) {
        const uint32_t aSt = smem_base + s * STAGE_BYTES;
        const uint32_t bSt = aSt + OPER_BYTES;
        const __nv_bfloat16* asrc = Ag + (size_t)lrow * RANK2 + c * BK + lh * 32;
        const __nv_bfloat16* bsrc = Bg + (size_t)lrow * RANK2 + c * BK + lh * 32;
#pragma unroll
        for (int q = 0; q < 4; q++) {
            uint32_t off = SWZ((uint32_t)(lrow * 128 + (lh * 4 + q) * 16));
            CP_ASYNC_CG(aSt + off, asrc + q * 8);
            CP_ASYNC_CG(bSt + off, bsrc + q * 8);
        }
    };

    float acc[4][4][4];
#pragma unroll
    for (int mt = 0; mt < 4; mt++)
#pragma unroll
        for (int nt = 0; nt < 4; nt++)
#pragma unroll
            for (int r = 0; r < 4; r++)
                acc[mt][nt][r] = 0.0f;

    load_chunk(0, 0);
    CP_ASYNC_COMMIT();
    load_chunk(1, 1);
    CP_ASYNC_COMMIT();

    // ldmatrix per-thread address components
    const int rowmA = l & 15;                 // row within 16-row m-tile
    const int colhA = (l >> 4) * 8;           // k-half (0 or 8)
    const int rowbB = ((l >> 4) * 8) + (l & 7);  // row within 16-row n-pair
    const int colhB = ((l >> 3) & 1) * 8;     // k-half

    for (int c = 0; c < NCHUNK; c++) {
        const int s = c & 1;
        if (c < NCHUNK - 1) { CP_ASYNC_WAIT1(); } else { CP_ASYNC_WAIT0(); }
        __syncthreads();

        const uint32_t aSt = smem_base + s * STAGE_BYTES;
        const uint32_t bSt = aSt + OPER_BYTES;

#pragma unroll
        for (int kk = 0; kk < 4; kk++) {      // 4 k16 steps per BK=64
            uint32_t a[4][4];
#pragma unroll
            for (int mt = 0; mt < 4; mt++) {
                uint32_t off = SWZ((uint32_t)((m0 + mt * 16 + rowmA) * 128 +
                                              (kk * 16 + colhA) * 2));
                LDSM_X4(a[mt][0], a[mt][1], a[mt][2], a[mt][3], aSt + off);
            }
            uint32_t bf[4][2];
#pragma unroll
            for (int p = 0; p < 2; p++) {
                uint32_t off = SWZ((uint32_t)((n0 + p * 16 + rowbB) * 128 +
                                              (kk * 16 + colhB) * 2));
                uint32_t r0, r1, r2, r3;
                LDSM_X4(r0, r1, r2, r3, bSt + off);
                bf[2 * p][0] = r0; bf[2 * p][1] = r1;
                bf[2 * p + 1][0] = r2; bf[2 * p + 1][1] = r3;
            }
#pragma unroll
            for (int mt = 0; mt < 4; mt++)
#pragma unroll
                for (int nt = 0; nt < 4; nt++)
                    MMA16816(acc[mt][nt], a[mt], bf[nt][0], bf[nt][1]);
        }

        __syncthreads();
        if (c + 2 < NCHUNK) {
            load_chunk(c + 2, s);
            CP_ASYNC_COMMIT();
        }
    }

    // ---- epilogue: d = ni + nj - 2*dot, clamp, float2 stores ----
    const int bS = b * SEQ;
    float njv[4][2];
#pragma unroll
    for (int nt = 0; nt < 4; nt++) {
        int j = j0 + n0 + nt * 8 + (l & 3) * 2;
        njv[nt][0] = g_sq_norms[bS + j];
        njv[nt][1] = g_sq_norms[bS + j + 1];
    }

#pragma unroll
    for (int mt = 0; mt < 4; mt++) {
#pragma unroll
        for (int hh = 0; hh < 2; hh++) {
            int i = i0 + m0 + mt * 16 + (l >> 2) + hh * 8;
            float ni = g_sq_norms[bS + i];
            float* orow = out + (size_t)(bS + i) * SEQ;
#pragma unroll
            for (int nt = 0; nt < 4; nt++) {
                int j = j0 + n0 + nt * 8 + (l & 3) * 2;
                float2 v;
                v.x = fmaxf(fmaf(-2.0f, acc[mt][nt][2 * hh],     ni + njv[nt][0]), 0.0f);
                v.y = fmaxf(fmaf(-2.0f, acc[mt][nt][2 * hh + 1], ni + njv[nt][1]), 0.0f);
                *reinterpret_cast<float2*>(orow + j) = v;
            }
        }
    }
}

// ---------------------------------------------------------------------------
extern "C" void kernel_launch(void* const* d_in, const int* in_sizes, int n_in,
                              void* d_out, int out_size) {
    (void)in_sizes; (void)n_in; (void)out_size;
    const float* x = (const float*)d_in[0];
    float* out = (float*)d_out;

    cudaFuncSetAttribute(dist_mma_kernel,
                         cudaFuncAttributeMaxDynamicSharedMemorySize, SMEM_TOTAL);

    prep_kernel<<<BATCH * SEQ / 4, 128>>>(x);

    dim3 grid(SEQ / 128, SEQ / 128, BATCH);   // (16, 16, 8)
    dist_mma_kernel<<<grid, 256, SMEM_TOTAL>>>(out);
}

// round 4
// speedup vs baseline: 2.5596x; 1.1154x over previous
#include <cuda_runtime.h>
#include <cuda_bf16.h>
#include <cstdint>

// d[b,i,j] = max(||x_i||^2 + ||x_j||^2 - 2 <x_i,x_j>, 0),  B=8, S=2048, K=256 fp32.
// hi/lo bf16 split concat along K (K'=512); mma.sync bf16 GEMM;
// 4-stage cp.async pipeline + register double-buffered ldmatrix frags.

#define BATCH 8
#define SEQ   2048
#define RANK  256
#define RANK2 512          // hi || lo

__device__ __nv_bfloat16 g_y[(size_t)BATCH * SEQ * RANK2];   // 16 MB
__device__ float g_sq_norms[BATCH * SEQ];

__device__ __forceinline__ uint32_t smem_to_u32(const void* p) {
    uint32_t a;
    asm("{ .reg .u64 t; cvta.to.shared.u64 t, %1; cvt.u32.u64 %0, t; }" : "=r"(a) : "l"(p));
    return a;
}
#define CP_ASYNC_CG(dst, src) \
    asm volatile("cp.async.cg.shared.global [%0], [%1], 16;" :: "r"(dst), "l"(src))
#define CP_ASYNC_COMMIT() asm volatile("cp.async.commit_group;" ::: "memory")
#define CP_ASYNC_WAIT2()  asm volatile("cp.async.wait_group 2;" ::: "memory")

#define LDSM_X4(r0, r1, r2, r3, addr) \
    asm volatile("ldmatrix.sync.aligned.m8n8.x4.shared.b16 {%0,%1,%2,%3}, [%4];" \
                 : "=r"(r0), "=r"(r1), "=r"(r2), "=r"(r3) : "r"(addr))

#define MMA16816(c, a, b0, b1) \
    asm volatile("mma.sync.aligned.m16n8k16.row.col.f32.bf16.bf16.f32 " \
                 "{%0,%1,%2,%3}, {%4,%5,%6,%7}, {%8,%9}, {%0,%1,%2,%3};" \
                 : "+f"((c)[0]), "+f"((c)[1]), "+f"((c)[2]), "+f"((c)[3]) \
                 : "r"((a)[0]), "r"((a)[1]), "r"((a)[2]), "r"((a)[3]), \
                   "r"(b0), "r"(b1))

#define SWZ(off) ((off) ^ (((off) >> 3) & 0x70))

// ---------------------------------------------------------------------------
// prep: fused hi/lo bf16 split + exact fp32 row norms. One warp per row.
// ---------------------------------------------------------------------------
__global__ __launch_bounds__(128) void prep_kernel(const float* __restrict__ x) {
    int row = blockIdx.x * 4 + (threadIdx.x >> 5);
    int lid = threadIdx.x & 31;
    const float* xr = x + (size_t)row * RANK + lid * 8;
    __nv_bfloat16* yr = g_y + (size_t)row * RANK2 + lid * 8;

    float4 v0 = *reinterpret_cast<const float4*>(xr);
    float4 v1 = *reinterpret_cast<const float4*>(xr + 4);

    float e[8] = {v0.x, v0.y, v0.z, v0.w, v1.x, v1.y, v1.z, v1.w};
    alignas(16) __nv_bfloat162 h[4];
    alignas(16) __nv_bfloat162 l[4];
    float s = 0.0f;
#pragma unroll
    for (int q = 0; q < 4; q++) {
        float a = e[2 * q], bvv = e[2 * q + 1];
        s = fmaf(a, a, s);
        s = fmaf(bvv, bvv, s);
        __nv_bfloat16 ha = __float2bfloat16_rn(a);
        __nv_bfloat16 hb = __float2bfloat16_rn(bvv);
        __nv_bfloat16 la = __float2bfloat16_rn(a - __bfloat162float(ha));
        __nv_bfloat16 lb = __float2bfloat16_rn(bvv - __bfloat162float(hb));
        h[q] = __nv_bfloat162(ha, hb);
        l[q] = __nv_bfloat162(la, lb);
    }
    *reinterpret_cast<uint4*>(yr)        = *reinterpret_cast<uint4*>(h);
    *reinterpret_cast<uint4*>(yr + RANK) = *reinterpret_cast<uint4*>(l);

#pragma unroll
    for (int m = 16; m > 0; m >>= 1) s += __shfl_xor_sync(0xffffffffu, s, m);
    if (lid == 0) g_sq_norms[row] = s;
}

// ---------------------------------------------------------------------------
// Main GEMM: 128x128 CTA tile, 8 warps (2x4), warp tile 64x32, BK=64,
// 4-stage cp.async ring, register double-buffered frags.
// ---------------------------------------------------------------------------
#define BK          64
#define NCHUNK      (RANK2 / BK)        // 8
#define STAGES      4
#define OPER_BYTES  16384               // 128 rows x 128 B
#define STAGE_BYTES 32768
#define SMEM_TOTAL  (STAGES * STAGE_BYTES)   // 128 KB

__global__ __launch_bounds__(256, 1)
void dist_mma_kernel(float* __restrict__ out) {
    extern __shared__ __align__(128) char smem[];
    const uint32_t smem_base = smem_to_u32(smem);

    const int t = threadIdx.x;
    const int l = t & 31;
    const int w = t >> 5;
    const int m0 = (w >> 2) * 64;
    const int n0 = (w & 3) * 32;

    const int b  = blockIdx.z;
    const int i0 = blockIdx.y * 128;
    const int j0 = blockIdx.x * 128;

    const __nv_bfloat16* __restrict__ Ag = g_y + (size_t)(b * SEQ + i0) * RANK2;
    const __nv_bfloat16* __restrict__ Bg = g_y + (size_t)(b * SEQ + j0) * RANK2;

    const int lrow = t >> 1;
    const int lh   = t & 1;

    auto load_chunk = [&](int c) {
        const uint32_t aSt = smem_base + (c & (STAGES - 1)) * STAGE_BYTES;
        const uint32_t bSt = aSt + OPER_BYTES;
        const __nv_bfloat16* asrc = Ag + (size_t)lrow * RANK2 + c * BK + lh * 32;
        const __nv_bfloat16* bsrc = Bg + (size_t)lrow * RANK2 + c * BK + lh * 32;
#pragma unroll
        for (int q = 0; q < 4; q++) {
            uint32_t off = SWZ((uint32_t)(lrow * 128 + (lh * 4 + q) * 16));
            CP_ASYNC_CG(aSt + off, asrc + q * 8);
            CP_ASYNC_CG(bSt + off, bsrc + q * 8);
        }
    };

    float acc[4][4][4];
#pragma unroll
    for (int mt = 0; mt < 4; mt++)
#pragma unroll
        for (int nt = 0; nt < 4; nt++)
#pragma unroll
            for (int r = 0; r < 4; r++)
                acc[mt][nt][r] = 0.0f;

    // prologue: fill 3 of 4 stages
    load_chunk(0); CP_ASYNC_COMMIT();
    load_chunk(1); CP_ASYNC_COMMIT();
    load_chunk(2); CP_ASYNC_COMMIT();

    // ldmatrix per-thread address components
    const int rowmA = l & 15;
    const int colhA = (l >> 4) * 8;
    const int rowbB = ((l >> 4) * 8) + (l & 7);
    const int colhB = ((l >> 3) & 1) * 8;

    uint32_t Abuf[2][4][4];
    uint32_t Bbuf[2][4][2];

    auto ldsm_frags = [&](int c, int kk, int pb) {
        const uint32_t aSt = smem_base + (c & (STAGES - 1)) * STAGE_BYTES;
        const uint32_t bSt = aSt + OPER_BYTES;
#pragma unroll
        for (int mt = 0; mt < 4; mt++) {
            uint32_t off = SWZ((uint32_t)((m0 + mt * 16 + rowmA) * 128 +
                                          (kk * 16 + colhA) * 2));
            LDSM_X4(Abuf[pb][mt][0], Abuf[pb][mt][1], Abuf[pb][mt][2], Abuf[pb][mt][3],
                    aSt + off);
        }
#pragma unroll
        for (int p = 0; p < 2; p++) {
            uint32_t off = SWZ((uint32_t)((n0 + p * 16 + rowbB) * 128 +
                                          (kk * 16 + colhB) * 2));
            uint32_t r0, r1, r2, r3;
            LDSM_X4(r0, r1, r2, r3, bSt + off);
            Bbuf[pb][2 * p][0] = r0;     Bbuf[pb][2 * p][1] = r1;
            Bbuf[pb][2 * p + 1][0] = r2; Bbuf[pb][2 * p + 1][1] = r3;
        }
    };

    // wait for stage 0, prefetch first frags
    CP_ASYNC_WAIT2();
    __syncthreads();
    ldsm_frags(0, 0, 0);

#pragma unroll 1
    for (int c = 0; c < NCHUNK; c++) {
#pragma unroll
        for (int kk = 0; kk < 4; kk++) {
            const int cur = kk & 1;
            const int nxt = cur ^ 1;
            if (kk < 3) {
                ldsm_frags(c, kk + 1, nxt);
            } else {
                // issue global loads for chunk c+3; rotate stage ring
                if (c + 3 < NCHUNK) load_chunk(c + 3);
                CP_ASYNC_COMMIT();
                if (c + 1 < NCHUNK) {
                    CP_ASYNC_WAIT2();
                    __syncthreads();
                    ldsm_frags(c + 1, 0, nxt);
                }
            }
#pragma unroll
            for (int mt = 0; mt < 4; mt++)
#pragma unroll
                for (int nt = 0; nt < 4; nt++)
                    MMA16816(acc[mt][nt], Abuf[cur][mt], Bbuf[cur][nt][0], Bbuf[cur][nt][1]);
        }
    }

    // ---- epilogue: d = ni + nj - 2*dot, clamp, float2 stores ----
    const int bS = b * SEQ;
    float njv[4][2];
#pragma unroll
    for (int nt = 0; nt < 4; nt++) {
        int j = j0 + n0 + nt * 8 + (l & 3) * 2;
        njv[nt][0] = g_sq_norms[bS + j];
        njv[nt][1] = g_sq_norms[bS + j + 1];
    }

#pragma unroll
    for (int mt = 0; mt < 4; mt++) {
#pragma unroll
        for (int hh = 0; hh < 2; hh++) {
            int i = i0 + m0 + mt * 16 + (l >> 2) + hh * 8;
            float ni = g_sq_norms[bS + i];
            float* orow = out + (size_t)(bS + i) * SEQ;
#pragma unroll
            for (int nt = 0; nt < 4; nt++) {
                int j = j0 + n0 + nt * 8 + (l & 3) * 2;
                float2 v;
                v.x = fmaxf(fmaf(-2.0f, acc[mt][nt][2 * hh],     ni + njv[nt][0]), 0.0f);
                v.y = fmaxf(fmaf(-2.0f, acc[mt][nt][2 * hh + 1], ni + njv[nt][1]), 0.0f);
                *reinterpret_cast<float2*>(orow + j) = v;
            }
        }
    }
}

// ---------------------------------------------------------------------------
extern "C" void kernel_launch(void* const* d_in, const int* in_sizes, int n_in,
                              void* d_out, int out_size) {
    (void)in_sizes; (void)n_in; (void)out_size;
    const float* x = (const float*)d_in[0];
    float* out = (float*)d_out;

    cudaFuncSetAttribute(dist_mma_kernel,
                         cudaFuncAttributeMaxDynamicSharedMemorySize, SMEM_TOTAL);

    prep_kernel<<<BATCH * SEQ / 4, 128>>>(x);

    dim3 grid(SEQ / 128, SEQ / 128, BATCH);   // (16, 16, 8)
    dist_mma_kernel<<<grid, 256, SMEM_TOTAL>>>(out);
}

// round 5
// speedup vs baseline: 3.1083x; 1.2143x over previous
#include <cuda_runtime.h>
#include <cuda_bf16.h>
#include <cstdint>

// d[b,i,j] = max(||x_i||^2 + ||x_j||^2 - 2 <x_i,x_j>, 0),  B=8, S=2048, K=256 fp32.
// hi/lo bf16 split concat along K (K'=512); mma.sync bf16 GEMM.
// R5: 3-stage ring (96KB) + 128-reg cap -> 2 CTAs/SM for latency hiding.

#define BATCH 8
#define SEQ   2048
#define RANK  256
#define RANK2 512          // hi || lo

__device__ __nv_bfloat16 g_y[(size_t)BATCH * SEQ * RANK2];   // 16 MB
__device__ float g_sq_norms[BATCH * SEQ];

__device__ __forceinline__ uint32_t smem_to_u32(const void* p) {
    uint32_t a;
    asm("{ .reg .u64 t; cvta.to.shared.u64 t, %1; cvt.u32.u64 %0, t; }" : "=r"(a) : "l"(p));
    return a;
}
#define CP_ASYNC_CG(dst, src) \
    asm volatile("cp.async.cg.shared.global [%0], [%1], 16;" :: "r"(dst), "l"(src))
#define CP_ASYNC_COMMIT() asm volatile("cp.async.commit_group;" ::: "memory")
#define CP_ASYNC_WAIT1()  asm volatile("cp.async.wait_group 1;" ::: "memory")

#define LDSM_X4(r0, r1, r2, r3, addr) \
    asm volatile("ldmatrix.sync.aligned.m8n8.x4.shared.b16 {%0,%1,%2,%3}, [%4];" \
                 : "=r"(r0), "=r"(r1), "=r"(r2), "=r"(r3) : "r"(addr))

#define MMA16816(c, a, b0, b1) \
    asm volatile("mma.sync.aligned.m16n8k16.row.col.f32.bf16.bf16.f32 " \
                 "{%0,%1,%2,%3}, {%4,%5,%6,%7}, {%8,%9}, {%0,%1,%2,%3};" \
                 : "+f"((c)[0]), "+f"((c)[1]), "+f"((c)[2]), "+f"((c)[3]) \
                 : "r"((a)[0]), "r"((a)[1]), "r"((a)[2]), "r"((a)[3]), \
                   "r"(b0), "r"(b1))

#define SWZ(off) ((off) ^ (((off) >> 3) & 0x70))

// ---------------------------------------------------------------------------
// prep: fused hi/lo bf16 split + exact fp32 row norms. One warp per row.
// ---------------------------------------------------------------------------
__global__ __launch_bounds__(128) void prep_kernel(const float* __restrict__ x) {
    int row = blockIdx.x * 4 + (threadIdx.x >> 5);
    int lid = threadIdx.x & 31;
    const float* xr = x + (size_t)row * RANK + lid * 8;
    __nv_bfloat16* yr = g_y + (size_t)row * RANK2 + lid * 8;

    float4 v0 = *reinterpret_cast<const float4*>(xr);
    float4 v1 = *reinterpret_cast<const float4*>(xr + 4);

    float e[8] = {v0.x, v0.y, v0.z, v0.w, v1.x, v1.y, v1.z, v1.w};
    alignas(16) __nv_bfloat162 h[4];
    alignas(16) __nv_bfloat162 l[4];
    float s = 0.0f;
#pragma unroll
    for (int q = 0; q < 4; q++) {
        float a = e[2 * q], bvv = e[2 * q + 1];
        s = fmaf(a, a, s);
        s = fmaf(bvv, bvv, s);
        __nv_bfloat16 ha = __float2bfloat16_rn(a);
        __nv_bfloat16 hb = __float2bfloat16_rn(bvv);
        __nv_bfloat16 la = __float2bfloat16_rn(a - __bfloat162float(ha));
        __nv_bfloat16 lb = __float2bfloat16_rn(bvv - __bfloat162float(hb));
        h[q] = __nv_bfloat162(ha, hb);
        l[q] = __nv_bfloat162(la, lb);
    }
    *reinterpret_cast<uint4*>(yr)        = *reinterpret_cast<uint4*>(h);
    *reinterpret_cast<uint4*>(yr + RANK) = *reinterpret_cast<uint4*>(l);

#pragma unroll
    for (int m = 16; m > 0; m >>= 1) s += __shfl_xor_sync(0xffffffffu, s, m);
    if (lid == 0) g_sq_norms[row] = s;
}

// ---------------------------------------------------------------------------
// Main GEMM: 128x128 CTA tile, 8 warps (2x4), warp tile 64x32, BK=64,
// 3-stage cp.async ring, 2 CTAs/SM.
// ---------------------------------------------------------------------------
#define BK          64
#define NCHUNK      (RANK2 / BK)        // 8
#define STAGES      3
#define OPER_BYTES  16384               // 128 rows x 128 B
#define STAGE_BYTES 32768
#define SMEM_TOTAL  (STAGES * STAGE_BYTES)   // 96 KB

__global__ __launch_bounds__(256, 2)
void dist_mma_kernel(float* __restrict__ out) {
    extern __shared__ __align__(128) char smem[];
    const uint32_t smem_base = smem_to_u32(smem);

    const int t = threadIdx.x;
    const int l = t & 31;
    const int w = t >> 5;
    const int m0 = (w >> 2) * 64;
    const int n0 = (w & 3) * 32;

    const int b  = blockIdx.z;
    const int i0 = blockIdx.y * 128;
    const int j0 = blockIdx.x * 128;

    const __nv_bfloat16* __restrict__ Ag = g_y + (size_t)(b * SEQ + i0) * RANK2;
    const __nv_bfloat16* __restrict__ Bg = g_y + (size_t)(b * SEQ + j0) * RANK2;

    const int lrow = t >> 1;
    const int lh   = t & 1;

    auto load_chunk = [&](int c, int s) {
        const uint32_t aSt = smem_base + s * STAGE_BYTES;
        const uint32_t bSt = aSt + OPER_BYTES;
        const __nv_bfloat16* asrc = Ag + (size_t)lrow * RANK2 + c * BK + lh * 32;
        const __nv_bfloat16* bsrc = Bg + (size_t)lrow * RANK2 + c * BK + lh * 32;
#pragma unroll
        for (int q = 0; q < 4; q++) {
            uint32_t off = SWZ((uint32_t)(lrow * 128 + (lh * 4 + q) * 16));
            CP_ASYNC_CG(aSt + off, asrc + q * 8);
            CP_ASYNC_CG(bSt + off, bsrc + q * 8);
        }
    };

    float acc[4][4][4];
#pragma unroll
    for (int mt = 0; mt < 4; mt++)
#pragma unroll
        for (int nt = 0; nt < 4; nt++)
#pragma unroll
            for (int r = 0; r < 4; r++)
                acc[mt][nt][r] = 0.0f;

    // prologue: 2 chunks in flight
    load_chunk(0, 0); CP_ASYNC_COMMIT();
    load_chunk(1, 1); CP_ASYNC_COMMIT();

    // ldmatrix per-thread address components
    const int rowmA = l & 15;
    const int colhA = (l >> 4) * 8;
    const int rowbB = ((l >> 4) * 8) + (l & 7);
    const int colhB = ((l >> 3) & 1) * 8;

    int stage = 0;                        // stage of chunk c
    int pstage = 2;                       // stage receiving chunk c+2

#pragma unroll 1
    for (int c = 0; c < NCHUNK; c++) {
        CP_ASYNC_WAIT1();
        __syncthreads();

        // issue next-next chunk loads into the stage freed by chunk c-1
        if (c + 2 < NCHUNK) load_chunk(c + 2, pstage);
        CP_ASYNC_COMMIT();

        const uint32_t aSt = smem_base + stage * STAGE_BYTES;
        const uint32_t bSt = aSt + OPER_BYTES;

#pragma unroll
        for (int kk = 0; kk < 4; kk++) {
            uint32_t a[4][4];
#pragma unroll
            for (int mt = 0; mt < 4; mt++) {
                uint32_t off = SWZ((uint32_t)((m0 + mt * 16 + rowmA) * 128 +
                                              (kk * 16 + colhA) * 2));
                LDSM_X4(a[mt][0], a[mt][1], a[mt][2], a[mt][3], aSt + off);
            }
            uint32_t bf[4][2];
#pragma unroll
            for (int p = 0; p < 2; p++) {
                uint32_t off = SWZ((uint32_t)((n0 + p * 16 + rowbB) * 128 +
                                              (kk * 16 + colhB) * 2));
                uint32_t r0, r1, r2, r3;
                LDSM_X4(r0, r1, r2, r3, bSt + off);
                bf[2 * p][0] = r0;     bf[2 * p][1] = r1;
                bf[2 * p + 1][0] = r2; bf[2 * p + 1][1] = r3;
            }
#pragma unroll
            for (int mt = 0; mt < 4; mt++)
#pragma unroll
                for (int nt = 0; nt < 4; nt++)
                    MMA16816(acc[mt][nt], a[mt], bf[nt][0], bf[nt][1]);
        }

        stage  = (stage  == STAGES - 1) ? 0 : stage + 1;
        pstage = (pstage == STAGES - 1) ? 0 : pstage + 1;
    }

    // ---- epilogue: d = ni + nj - 2*dot, clamp, float2 stores ----
    const int bS = b * SEQ;
    float njv[4][2];
#pragma unroll
    for (int nt = 0; nt < 4; nt++) {
        int j = j0 + n0 + nt * 8 + (l & 3) * 2;
        njv[nt][0] = g_sq_norms[bS + j];
        njv[nt][1] = g_sq_norms[bS + j + 1];
    }

#pragma unroll
    for (int mt = 0; mt < 4; mt++) {
#pragma unroll
        for (int hh = 0; hh < 2; hh++) {
            int i = i0 + m0 + mt * 16 + (l >> 2) + hh * 8;
            float ni = g_sq_norms[bS + i];
            float* orow = out + (size_t)(bS + i) * SEQ;
#pragma unroll
            for (int nt = 0; nt < 4; nt++) {
                int j = j0 + n0 + nt * 8 + (l & 3) * 2;
                float2 v;
                v.x = fmaxf(fmaf(-2.0f, acc[mt][nt][2 * hh],     ni + njv[nt][0]), 0.0f);
                v.y = fmaxf(fmaf(-2.0f, acc[mt][nt][2 * hh + 1], ni + njv[nt][1]), 0.0f);
                *reinterpret_cast<float2*>(orow + j) = v;
            }
        }
    }
}

// ---------------------------------------------------------------------------
extern "C" void kernel_launch(void* const* d_in, const int* in_sizes, int n_in,
                              void* d_out, int out_size) {
    (void)in_sizes; (void)n_in; (void)out_size;
    const float* x = (const float*)d_in[0];
    float* out = (float*)d_out;

    cudaFuncSetAttribute(dist_mma_kernel,
                         cudaFuncAttributeMaxDynamicSharedMemorySize, SMEM_TOTAL);

    prep_kernel<<<BATCH * SEQ / 4, 128>>>(x);

    dim3 grid(SEQ / 128, SEQ / 128, BATCH);   // (16, 16, 8)
    dist_mma_kernel<<<grid, 256, SMEM_TOTAL>>>(out);
}